// round 10
// baseline (speedup 1.0000x reference)
#include <cuda_runtime.h>
#include <math.h>

#define NSTEPS 64
#define BM     32
#define GRID   256   // 8192 / 32

// Tsit5 tableau in constant memory (stage loop is rolled; runtime-indexed)
__constant__ float c_A[6][5] = {
    {0.f, 0.f, 0.f, 0.f, 0.f},
    {0.161f, 0.f, 0.f, 0.f, 0.f},
    {-0.008480655492356989f, 0.335480655492357f, 0.f, 0.f, 0.f},
    {2.8971530571054935f, -6.359448489975075f, 4.3622954328695815f, 0.f, 0.f},
    {5.325864828439257f, -11.748883564062828f, 7.4955393428898365f, -0.09249506636175525f, 0.f},
    {5.86145544294642f, -12.92096931784711f, 8.159367898576159f, -0.071584973281401f, -0.028269050394068383f},
};
__constant__ float c_B[6] = {
    0.09646076681806523f, 0.01f, 0.4798896504144996f,
    1.379008574103742f, -3.290069515436081f, 2.324710524099774f
};

// SMEM layout (floats): sX[32*128] | sH[32*512] | sT[32*128] | sW[2*32*128] | sK[6*32*128]
#define OFF_X 0
#define OFF_H 4096
#define OFF_T 20480
#define OFF_W 24576
#define OFF_K 32768
#define SMEM_FLOATS 57344   // 224 KB (< 232448-byte sm_103a opt-in cap)

__device__ __forceinline__ void cp16(float* dst, const float* src) {
    unsigned d = (unsigned)__cvta_generic_to_shared(dst);
    asm volatile("cp.async.cg.shared.global [%0], [%1], 16;" :: "r"(d), "l"(src));
}
__device__ __forceinline__ void cp_commit() { asm volatile("cp.async.commit_group;"); }
__device__ __forceinline__ void cp_wait0()  { asm volatile("cp.async.wait_group 0;" ::: "memory"); }

// C[32 x 128] (+)= sIn[32 x 32*NSL] @ gW[32*NSL x 128]
// gW: global, row stride ldw floats (chunk column base pre-folded into gW).
// sIn: SMEM, row stride ldin. sW: two 4096-float double buffers.
// Thread (rg = tid>>5, c0 = (tid&31)*4) owns rows rg*4..+3, cols c0..+3.
// All barriers are block-uniform (no divergence): safe.
template <int NSL>
__device__ __forceinline__ void gemm_block(
    const float* __restrict__ gW, int ldw,
    const float* __restrict__ sIn, int ldin,
    float* __restrict__ sW,
    float (&acc)[4][4], int rg, int c0)
{
    __syncthreads();   // protect sW buffers (and make sIn writes visible)

    // preload slice 0 into buffer 0
#pragma unroll
    for (int q = 0; q < 4; q++) {
        int r = q * 8 + rg;
        cp16(sW + r * 128 + c0, gW + (size_t)r * ldw + c0);
    }
    cp_commit();

#pragma unroll 1
    for (int t = 0; t < NSL; t++) {
        cp_wait0();        // slice t landed
        __syncthreads();   // visible to all; all done with buf being refilled next

        if (t + 1 < NSL) {
            const float* g = gW + (size_t)(t + 1) * 32 * ldw;
            float* buf = sW + ((t + 1) & 1) * 4096;
#pragma unroll
            for (int q = 0; q < 4; q++) {
                int r = q * 8 + rg;
                cp16(buf + r * 128 + c0, g + (size_t)r * ldw + c0);
            }
            cp_commit();
        }

        const float* buf = sW + (t & 1) * 4096;
        const float* Ab  = sIn + (rg * 4) * ldin + t * 32;
#pragma unroll
        for (int k4 = 0; k4 < 32; k4 += 4) {
            // A operands: lane-invariant (broadcast), vectorized over 4 k
            float4 a0 = *(const float4*)(Ab + 0 * ldin + k4);
            float4 a1 = *(const float4*)(Ab + 1 * ldin + k4);
            float4 a2 = *(const float4*)(Ab + 2 * ldin + k4);
            float4 a3 = *(const float4*)(Ab + 3 * ldin + k4);
#pragma unroll
            for (int u = 0; u < 4; u++) {
                float4 w = *(const float4*)(buf + (k4 + u) * 128 + c0);
                float e0 = (&a0.x)[u], e1 = (&a1.x)[u], e2 = (&a2.x)[u], e3 = (&a3.x)[u];
                acc[0][0] = fmaf(e0, w.x, acc[0][0]);
                acc[0][1] = fmaf(e0, w.y, acc[0][1]);
                acc[0][2] = fmaf(e0, w.z, acc[0][2]);
                acc[0][3] = fmaf(e0, w.w, acc[0][3]);
                acc[1][0] = fmaf(e1, w.x, acc[1][0]);
                acc[1][1] = fmaf(e1, w.y, acc[1][1]);
                acc[1][2] = fmaf(e1, w.z, acc[1][2]);
                acc[1][3] = fmaf(e1, w.w, acc[1][3]);
                acc[2][0] = fmaf(e2, w.x, acc[2][0]);
                acc[2][1] = fmaf(e2, w.y, acc[2][1]);
                acc[2][2] = fmaf(e2, w.z, acc[2][2]);
                acc[2][3] = fmaf(e2, w.w, acc[2][3]);
                acc[3][0] = fmaf(e3, w.x, acc[3][0]);
                acc[3][1] = fmaf(e3, w.y, acc[3][1]);
                acc[3][2] = fmaf(e3, w.z, acc[3][2]);
                acc[3][3] = fmaf(e3, w.w, acc[3][3]);
            }
        }
    }
}

__global__ __launch_bounds__(256, 1)
void ode_fused(const float* __restrict__ y0, const float* __restrict__ ts,
               const float* __restrict__ W1, const float* __restrict__ b1,
               const float* __restrict__ W2, const float* __restrict__ b2,
               const float* __restrict__ W3, const float* __restrict__ b3,
               float* __restrict__ out)
{
    extern __shared__ float sm[];
    float* sX = sm + OFF_X;
    float* sH = sm + OFF_H;
    float* sT = sm + OFF_T;
    float* sW = sm + OFF_W;
    float* sK = sm + OFF_K;

    const int tid  = threadIdx.x;
    const int rg   = tid >> 5;          // warp id 0..7 -> rows rg*4..+3
    const int c0   = (tid & 31) * 4;    // col base 0..124
    const int r0   = rg * 4;
    const int grow = blockIdx.x * BM + r0;

    const float dt = (ts[1] - ts[0]) * (1.0f / NSTEPS);

    // y in registers (thread-local 4 rows x 4 cols)
    float y[4][4];
#pragma unroll
    for (int i = 0; i < 4; i++) {
        float4 v = *(const float4*)(y0 + (size_t)(grow + i) * 128 + c0);
        y[i][0] = v.x; y[i][1] = v.y; y[i][2] = v.z; y[i][3] = v.w;
    }

#pragma unroll 1
    for (int step = 0; step < NSTEPS; step++) {
#pragma unroll 1
        for (int s = 0; s < 6; s++) {
            // ---- stage input x = y + dt * sum_{j<s} A[s][j] * k_j  -> sX
            // (all sK reads are this thread's own positions: no sync needed)
#pragma unroll
            for (int i = 0; i < 4; i++) {
                float4 x = make_float4(y[i][0], y[i][1], y[i][2], y[i][3]);
#pragma unroll 1
                for (int j = 0; j < s; j++) {
                    float cj = dt * c_A[s][j];
                    float4 kv = *(const float4*)(sK + j * 4096 + (r0 + i) * 128 + c0);
                    x.x = fmaf(cj, kv.x, x.x);
                    x.y = fmaf(cj, kv.y, x.y);
                    x.z = fmaf(cj, kv.z, x.z);
                    x.w = fmaf(cj, kv.w, x.w);
                }
                *(float4*)(sX + (r0 + i) * 128 + c0) = x;
            }

            // ---- layer 1: h1 = tanh(x @ W1 + b1)   [32x128]@[128x512]
#pragma unroll 1
            for (int nc = 0; nc < 4; nc++) {
                float acc[4][4] = {};
                gemm_block<4>(W1 + nc * 128, 512, sX, 128, sW, acc, rg, c0);
                float4 bb = *(const float4*)(b1 + nc * 128 + c0);
#pragma unroll
                for (int i = 0; i < 4; i++) {
                    float4 r;
                    r.x = tanhf(acc[i][0] + bb.x);
                    r.y = tanhf(acc[i][1] + bb.y);
                    r.z = tanhf(acc[i][2] + bb.z);
                    r.w = tanhf(acc[i][3] + bb.w);
                    *(float4*)(sH + (r0 + i) * 512 + nc * 128 + c0) = r;
                }
            }

            // ---- layer 2 + layer 3 fused (h2 never fully materialized):
            // per 128-col chunk of h2: t = tanh(h1 @ W2[:,chunk] + b2[chunk]);
            // kacc += t @ W3[chunk,:]
            float kacc[4][4] = {};
#pragma unroll 1
            for (int nc = 0; nc < 4; nc++) {
                float acc[4][4] = {};
                gemm_block<16>(W2 + nc * 128, 512, sH, 512, sW, acc, rg, c0);
                float4 bb = *(const float4*)(b2 + nc * 128 + c0);
#pragma unroll
                for (int i = 0; i < 4; i++) {
                    float4 r;
                    r.x = tanhf(acc[i][0] + bb.x);
                    r.y = tanhf(acc[i][1] + bb.y);
                    r.z = tanhf(acc[i][2] + bb.z);
                    r.w = tanhf(acc[i][3] + bb.w);
                    *(float4*)(sT + (r0 + i) * 128 + c0) = r;
                }
                // leading __syncthreads inside gemm_block makes sT visible
                gemm_block<4>(W3 + (size_t)nc * 128 * 128, 128, sT, 128, sW, kacc, rg, c0);
            }

            // ---- k_s = kacc + b3 -> sK[s] (thread-local positions)
            {
                float4 b3v = *(const float4*)(b3 + c0);
#pragma unroll
                for (int i = 0; i < 4; i++) {
                    float4 kv;
                    kv.x = kacc[i][0] + b3v.x;
                    kv.y = kacc[i][1] + b3v.y;
                    kv.z = kacc[i][2] + b3v.z;
                    kv.w = kacc[i][3] + b3v.w;
                    *(float4*)(sK + s * 4096 + (r0 + i) * 128 + c0) = kv;
                }
            }
        }

        // ---- y += dt * sum_j B[j] * k_j (thread-local reads of sK)
#pragma unroll
        for (int i = 0; i < 4; i++) {
            float4 a = make_float4(0.f, 0.f, 0.f, 0.f);
#pragma unroll
            for (int j = 0; j < 6; j++) {
                float cj = c_B[j];
                float4 kv = *(const float4*)(sK + j * 4096 + (r0 + i) * 128 + c0);
                a.x = fmaf(cj, kv.x, a.x);
                a.y = fmaf(cj, kv.y, a.y);
                a.z = fmaf(cj, kv.z, a.z);
                a.w = fmaf(cj, kv.w, a.w);
            }
            y[i][0] = fmaf(dt, a.x, y[i][0]);
            y[i][1] = fmaf(dt, a.y, y[i][1]);
            y[i][2] = fmaf(dt, a.z, y[i][2]);
            y[i][3] = fmaf(dt, a.w, y[i][3]);
        }
    }

    // final write
#pragma unroll
    for (int i = 0; i < 4; i++) {
        float4 v = make_float4(y[i][0], y[i][1], y[i][2], y[i][3]);
        *(float4*)(out + (size_t)(grow + i) * 128 + c0) = v;
    }
}

extern "C" void kernel_launch(void* const* d_in, const int* in_sizes, int n_in,
                              void* d_out, int out_size)
{
    const float* y0 = (const float*)d_in[0];
    const float* ts = (const float*)d_in[1];
    const float* W1 = (const float*)d_in[2];
    const float* b1 = (const float*)d_in[3];
    const float* W2 = (const float*)d_in[4];
    const float* b2 = (const float*)d_in[5];
    const float* W3 = (const float*)d_in[6];
    const float* b3 = (const float*)d_in[7];
    float* out = (float*)d_out;

    const int smem_bytes = SMEM_FLOATS * (int)sizeof(float);  // 229376
    cudaFuncSetAttribute(ode_fused, cudaFuncAttributeMaxDynamicSharedMemorySize, smem_bytes);

    // single kernel launch = single graph node: no multi-MB graph upload buffer
    ode_fused<<<GRID, 256, smem_bytes>>>(y0, ts, W1, b1, W2, b2, W3, b3, out);
}

// round 11
// speedup vs baseline: 1.3352x; 1.3352x over previous
#include <cuda_runtime.h>
#include <math.h>

#define NSTEPS 64
#define BM     64
#define GRID   128   // 8192 / 64

// Tsit5 tableau in constant memory
__constant__ float c_A[6][5] = {
    {0.f, 0.f, 0.f, 0.f, 0.f},
    {0.161f, 0.f, 0.f, 0.f, 0.f},
    {-0.008480655492356989f, 0.335480655492357f, 0.f, 0.f, 0.f},
    {2.8971530571054935f, -6.359448489975075f, 4.3622954328695815f, 0.f, 0.f},
    {5.325864828439257f, -11.748883564062828f, 7.4955393428898365f, -0.09249506636175525f, 0.f},
    {5.86145544294642f, -12.92096931784711f, 8.159367898576159f, -0.071584973281401f, -0.028269050394068383f},
};
__constant__ float c_B[6] = {
    0.09646076681806523f, 0.01f, 0.4798896504144996f,
    1.379008574103742f, -3.290069515436081f, 2.324710524099774f
};

// k stages live in global scratch (L2-resident: 25 MB), thread-local access only
__device__ float g_k[6 * 8192 * 128];

// SMEM (floats): sXT[64*128] (sX aliased with sT) | sH[64*512] | sW[2*32*128]
#define OFF_XT 0
#define OFF_H  8192
#define OFF_W  40960
#define SMEM_FLOATS 49152   // 192 KB

typedef unsigned long long u64t;

__device__ __forceinline__ void cp16(float* dst, const float* src) {
    unsigned d = (unsigned)__cvta_generic_to_shared(dst);
    asm volatile("cp.async.cg.shared.global [%0], [%1], 16;" :: "r"(d), "l"(src));
}
__device__ __forceinline__ void cp_commit() { asm volatile("cp.async.commit_group;"); }
__device__ __forceinline__ void cp_wait0()  { asm volatile("cp.async.wait_group 0;" ::: "memory"); }

// packed f32x2 helpers
__device__ __forceinline__ u64t dup2(float a) {
    u64t d; asm("mov.b64 %0, {%1, %1};" : "=l"(d) : "f"(a)); return d;
}
__device__ __forceinline__ float2 unpk(u64t v) {
    float2 r; asm("mov.b64 {%0, %1}, %2;" : "=f"(r.x), "=f"(r.y) : "l"(v)); return r;
}
#define FMA2(acc, a, b) asm("fma.rn.f32x2 %0, %1, %2, %0;" : "+l"(acc) : "l"(a), "l"(b))

// C[64 x 128] (+)= sIn[64 x 32*NSL] @ gW[32*NSL x 128]
// Thread (rg = tid>>5 -> rows rg*8..+7, c0 = (tid&31)*4 -> cols c0..+3).
// Accumulators: packed f32x2 pairs acc[8 rows][2 col-pairs].
// All barriers block-uniform.
template <int NSL>
__device__ __forceinline__ void gemm_block(
    const float* __restrict__ gW, int ldw,
    const float* __restrict__ sIn, int ldin,
    float* __restrict__ sW,
    u64t (&acc)[8][2], int rg, int c0)
{
    __syncthreads();   // protect sW buffers; make sIn writes visible

    // preload slice 0 into buffer 0
#pragma unroll
    for (int q = 0; q < 4; q++) {
        int r = q * 8 + rg;
        cp16(sW + r * 128 + c0, gW + (size_t)r * ldw + c0);
    }
    cp_commit();

#pragma unroll 1
    for (int t = 0; t < NSL; t++) {
        cp_wait0();        // slice t landed
        __syncthreads();   // visible to all; all warps done with prior slice

        if (t + 1 < NSL) {
            const float* g = gW + (size_t)(t + 1) * 32 * ldw;
            float* buf = sW + ((t + 1) & 1) * 4096;
#pragma unroll
            for (int q = 0; q < 4; q++) {
                int r = q * 8 + rg;
                cp16(buf + r * 128 + c0, g + (size_t)r * ldw + c0);
            }
            cp_commit();
        }

        const float* buf = sW + (t & 1) * 4096;
        const float* Ab  = sIn + (rg * 8) * ldin + t * 32;
#pragma unroll
        for (int k4 = 0; k4 < 32; k4 += 4) {
            float4 a[8];
#pragma unroll
            for (int i = 0; i < 8; i++)
                a[i] = *(const float4*)(Ab + i * ldin + k4);
#pragma unroll
            for (int u = 0; u < 4; u++) {
                // W pair operands straight from LDS.128 (two packed f32x2)
                ulonglong2 w = *(const ulonglong2*)(buf + (k4 + u) * 128 + c0);
#pragma unroll
                for (int i = 0; i < 8; i++) {
                    u64t ad = dup2((&a[i].x)[u]);
                    FMA2(acc[i][0], ad, w.x);
                    FMA2(acc[i][1], ad, w.y);
                }
            }
        }
    }
}

__global__ __launch_bounds__(256, 1)
void ode_fused(const float* __restrict__ y0, const float* __restrict__ ts,
               const float* __restrict__ W1, const float* __restrict__ b1,
               const float* __restrict__ W2, const float* __restrict__ b2,
               const float* __restrict__ W3, const float* __restrict__ b3,
               float* __restrict__ out)
{
    extern __shared__ float sm[];
    float* sXT = sm + OFF_XT;   // stage input x (during L1); h2 chunk t (during L2/L3)
    float* sH  = sm + OFF_H;
    float* sW  = sm + OFF_W;

    const int tid  = threadIdx.x;
    const int rg   = tid >> 5;          // warp id 0..7 -> rows rg*8..+7
    const int c0   = (tid & 31) * 4;    // col base 0..124
    const int r0   = rg * 8;
    const int grow = blockIdx.x * BM + r0;

    const float dt = (ts[1] - ts[0]) * (1.0f / NSTEPS);

    // y in registers: 8 rows x 4 cols per thread
    float y[8][4];
#pragma unroll
    for (int i = 0; i < 8; i++) {
        float4 v = *(const float4*)(y0 + (size_t)(grow + i) * 128 + c0);
        y[i][0] = v.x; y[i][1] = v.y; y[i][2] = v.z; y[i][3] = v.w;
    }

    // this thread's k-scratch base (row-major [6][8192][128])
    float* kbase = g_k + (size_t)(grow) * 128 + c0;
#define KPTR(j, i) (kbase + (size_t)(j) * 8192 * 128 + (i) * 128)

#pragma unroll 1
    for (int step = 0; step < NSTEPS; step++) {
#pragma unroll 1
        for (int s = 0; s < 6; s++) {
            // barrier: prior stage's L3 reads of sXT (as sT) must complete
            __syncthreads();

            // ---- stage input x = y + dt * sum_{j<s} A[s][j] * k_j  -> sXT
#pragma unroll
            for (int i = 0; i < 8; i++) {
                float4 x = make_float4(y[i][0], y[i][1], y[i][2], y[i][3]);
#pragma unroll 1
                for (int j = 0; j < s; j++) {
                    float cj = dt * c_A[s][j];
                    float4 kv = *(const float4*)KPTR(j, i);
                    x.x = fmaf(cj, kv.x, x.x);
                    x.y = fmaf(cj, kv.y, x.y);
                    x.z = fmaf(cj, kv.z, x.z);
                    x.w = fmaf(cj, kv.w, x.w);
                }
                *(float4*)(sXT + (r0 + i) * 128 + c0) = x;
            }

            // ---- layer 1: h1 = tanh(x @ W1 + b1)   [64x128]@[128x512]
#pragma unroll 1
            for (int nc = 0; nc < 4; nc++) {
                u64t acc[8][2] = {};
                gemm_block<4>(W1 + nc * 128, 512, sXT, 128, sW, acc, rg, c0);
                float4 bb = *(const float4*)(b1 + nc * 128 + c0);
#pragma unroll
                for (int i = 0; i < 8; i++) {
                    float2 p0 = unpk(acc[i][0]);
                    float2 p1 = unpk(acc[i][1]);
                    float4 r;
                    r.x = tanhf(p0.x + bb.x);
                    r.y = tanhf(p0.y + bb.y);
                    r.z = tanhf(p1.x + bb.z);
                    r.w = tanhf(p1.y + bb.w);
                    *(float4*)(sH + (r0 + i) * 512 + nc * 128 + c0) = r;
                }
            }

            // ---- layer 2 + 3 fused: per h2 chunk, t=tanh(h1@W2c+b2c); kacc += t@W3c
            u64t kacc[8][2] = {};
#pragma unroll 1
            for (int nc = 0; nc < 4; nc++) {
                u64t acc[8][2] = {};
                gemm_block<16>(W2 + nc * 128, 512, sH, 512, sW, acc, rg, c0);
                float4 bb = *(const float4*)(b2 + nc * 128 + c0);
#pragma unroll
                for (int i = 0; i < 8; i++) {
                    float2 p0 = unpk(acc[i][0]);
                    float2 p1 = unpk(acc[i][1]);
                    float4 r;
                    r.x = tanhf(p0.x + bb.x);
                    r.y = tanhf(p0.y + bb.y);
                    r.z = tanhf(p1.x + bb.z);
                    r.w = tanhf(p1.y + bb.w);
                    *(float4*)(sXT + (r0 + i) * 128 + c0) = r;  // sT
                }
                // leading __syncthreads inside gemm_block makes sT visible
                gemm_block<4>(W3 + (size_t)nc * 128 * 128, 128, sXT, 128, sW, kacc, rg, c0);
            }

            // ---- k_s = kacc + b3 -> global scratch (thread-local positions)
            {
                float4 b3v = *(const float4*)(b3 + c0);
#pragma unroll
                for (int i = 0; i < 8; i++) {
                    float2 p0 = unpk(kacc[i][0]);
                    float2 p1 = unpk(kacc[i][1]);
                    float4 kv;
                    kv.x = p0.x + b3v.x;
                    kv.y = p0.y + b3v.y;
                    kv.z = p1.x + b3v.z;
                    kv.w = p1.y + b3v.w;
                    *(float4*)KPTR(s, i) = kv;
                }
            }
        }

        // ---- y += dt * sum_j B[j] * k_j (thread-local reads; same-thread RAW)
#pragma unroll
        for (int i = 0; i < 8; i++) {
            float4 a = make_float4(0.f, 0.f, 0.f, 0.f);
#pragma unroll
            for (int j = 0; j < 6; j++) {
                float cj = c_B[j];
                float4 kv = *(const float4*)KPTR(j, i);
                a.x = fmaf(cj, kv.x, a.x);
                a.y = fmaf(cj, kv.y, a.y);
                a.z = fmaf(cj, kv.z, a.z);
                a.w = fmaf(cj, kv.w, a.w);
            }
            y[i][0] = fmaf(dt, a.x, y[i][0]);
            y[i][1] = fmaf(dt, a.y, y[i][1]);
            y[i][2] = fmaf(dt, a.z, y[i][2]);
            y[i][3] = fmaf(dt, a.w, y[i][3]);
        }
    }

    // final write
#pragma unroll
    for (int i = 0; i < 8; i++) {
        float4 v = make_float4(y[i][0], y[i][1], y[i][2], y[i][3]);
        *(float4*)(out + (size_t)(grow + i) * 128 + c0) = v;
    }
#undef KPTR
}

extern "C" void kernel_launch(void* const* d_in, const int* in_sizes, int n_in,
                              void* d_out, int out_size)
{
    const float* y0 = (const float*)d_in[0];
    const float* ts = (const float*)d_in[1];
    const float* W1 = (const float*)d_in[2];
    const float* b1 = (const float*)d_in[3];
    const float* W2 = (const float*)d_in[4];
    const float* b2 = (const float*)d_in[5];
    const float* W3 = (const float*)d_in[6];
    const float* b3 = (const float*)d_in[7];
    float* out = (float*)d_out;

    const int smem_bytes = SMEM_FLOATS * (int)sizeof(float);  // 196608
    cudaFuncSetAttribute(ode_fused, cudaFuncAttributeMaxDynamicSharedMemorySize, smem_bytes);

    // single kernel launch = single graph node
    ode_fused<<<GRID, 256, smem_bytes>>>(y0, ts, W1, b1, W2, b2, W3, b3, out);
}